// round 1
// baseline (speedup 1.0000x reference)
#include <cuda_runtime.h>
#include <cuda_bf16.h>
#include <cstddef>

// Problem constants (fixed by the reference: L=16, K=2, V=2, B=512)
#define S_  65536   // 1 << L
#define R_  4096    // 1 << (L - KV)
#define D_  16      // 1 << KV
#define B_  512
#define PS_ (B_ * R_)        // prev_state element count = 2097152
#define NC_ ((size_t)B_ * S_) // new_cost element count  = 33554432

// One thread handles 4 consecutive r's (rq = r/4 in [0, 1024)).
// cost[b] viewed as [16][4096] (d-major stripes of 4096 floats):
//   cand_cost[b, r, d] = cost[b][d*4096 + r]  since sc[r,d] = r + 4096*d.
__global__ __launch_bounds__(256)
void trellis_fused_kernel(const float*  __restrict__ lut,   // [S,2]
                          const float*  __restrict__ cost,  // [B,S]
                          const float*  __restrict__ orig,  // [B,2]
                          const int*    __restrict__ sc,    // [R,16]
                          float*        __restrict__ ps_out, // [B,R] or null
                          float*        __restrict__ nc_out) // [B,S] or null
{
    const int gid = blockIdx.x * blockDim.x + threadIdx.x; // 0 .. B_*1024-1
    const int b   = gid >> 10;       // 1024 float4-groups per batch row
    const int rq  = gid & 1023;

    const float4* __restrict__ cbv = (const float4*)(cost + (size_t)b * S_);

    // ---- min / argmin over d (strict '<' => first-occurrence like jnp.argmin)
    float4 best = cbv[rq];
    int bdx = 0, bdy = 0, bdz = 0, bdw = 0;
    #pragma unroll
    for (int d = 1; d < D_; ++d) {
        float4 v = cbv[d * (R_ / 4) + rq];
        if (v.x < best.x) { best.x = v.x; bdx = d; }
        if (v.y < best.y) { best.y = v.y; bdy = d; }
        if (v.z < best.z) { best.z = v.z; bdz = d; }
        if (v.w < best.w) { best.w = v.w; bdw = d; }
    }

    const int r0 = rq << 2;

    // ---- prev_state[b, r] = sc[r, best_idx]  (L2-resident gather)
    if (ps_out) {
        float4 ps;
        ps.x = (float)__ldg(&sc[(r0 + 0) * D_ + bdx]);
        ps.y = (float)__ldg(&sc[(r0 + 1) * D_ + bdy]);
        ps.z = (float)__ldg(&sc[(r0 + 2) * D_ + bdz]);
        ps.w = (float)__ldg(&sc[(r0 + 3) * D_ + bdw]);
        ((float4*)ps_out)[(size_t)b * (R_ / 4) + rq] = ps;
    }

    // ---- new_cost[b, r*16+d] = (lut[s,0]-o0)^2 + (lut[s,1]-o1)^2 + best_val[b,r]
    if (nc_out) {
        const float o0 = __ldg(&orig[2 * b + 0]);
        const float o1 = __ldg(&orig[2 * b + 1]);
        const float bests[4] = { best.x, best.y, best.z, best.w };

        // this thread covers s = [64*rq, 64*rq + 64): 16 float4 stores
        float4* __restrict__ nc = (float4*)(nc_out + (size_t)b * S_) + (size_t)rq * 16;
        const float4* __restrict__ lrow = (const float4*)lut + (size_t)r0 * 8; // 8 float4 per r

        #pragma unroll
        for (int i = 0; i < 4; ++i) {          // per r
            const float bv = bests[i];
            #pragma unroll
            for (int j = 0; j < 4; ++j) {      // 4 new_cost values per iter
                float4 l0 = __ldg(&lrow[i * 8 + j * 2 + 0]); // lut pairs s, s+1
                float4 l1 = __ldg(&lrow[i * 8 + j * 2 + 1]); // lut pairs s+2, s+3
                float4 o;
                float dx, dy;
                dx = l0.x - o0; dy = l0.y - o1; o.x = fmaf(dx, dx, dy * dy) + bv;
                dx = l0.z - o0; dy = l0.w - o1; o.y = fmaf(dx, dx, dy * dy) + bv;
                dx = l1.x - o0; dy = l1.y - o1; o.z = fmaf(dx, dx, dy * dy) + bv;
                dx = l1.z - o0; dy = l1.w - o1; o.w = fmaf(dx, dx, dy * dy) + bv;
                nc[i * 4 + j] = o;
            }
        }
    }
}

extern "C" void kernel_launch(void* const* d_in, const int* in_sizes, int n_in,
                              void* d_out, int out_size)
{
    const float* lut  = (const float*)d_in[0]; // training_lut [S,2]
    const float* cost = (const float*)d_in[1]; // cost [B,S]
    const float* orig = (const float*)d_in[2]; // orig_seq_part [B,2]
    const int*   sc   = (const int*)d_in[3];   // state_candidates [R,16]
    float* out = (float*)d_out;

    // Expected: flattened tuple (prev_state [B,R], new_cost [B,S]) as float32.
    // Guard on out_size so single-tensor layouts still work.
    float* ps_out = nullptr;
    float* nc_out = nullptr;
    const size_t osz = (size_t)out_size;
    if (osz >= (size_t)PS_ + NC_) {
        ps_out = out;
        nc_out = out + PS_;
    } else if (osz == NC_) {
        nc_out = out;
    } else {
        ps_out = out; // prev_state only
    }

    const int total_groups = B_ * (R_ / 4);   // 524288 threads
    trellis_fused_kernel<<<total_groups / 256, 256>>>(lut, cost, orig, sc,
                                                      ps_out, nc_out);
}

// round 4
// speedup vs baseline: 1.5391x; 1.5391x over previous
#include <cuda_runtime.h>
#include <cuda_bf16.h>
#include <cstddef>

// Problem constants (fixed by reference: L=16, KV=4, V=2, B=512)
#define S_  65536
#define R_  4096
#define D_  16
#define B_  512
#define PS_ (B_ * R_)          // 2097152
#define NC_ ((size_t)B_ * S_)  // 33554432

// Block = 256 threads, covers 256 rq (= 1024 r's = 16384 s's) of one batch row.
// Phase 1: per-thread min/argmin over d for 4 consecutive r's (coalesced strided
//          float4 loads, MLP=16), write prev_state (coalesced), stash best_val
//          in smem.
// Phase 2: coalesced epilogue — thread t writes float4 nc[it*256+t]; lut reads
//          are 32B/thread contiguous; best_val broadcast from smem.
__global__ __launch_bounds__(256)
void trellis_fused_kernel(const float*  __restrict__ lut,   // [S,2]
                          const float*  __restrict__ cost,  // [B,S]
                          const float*  __restrict__ orig,  // [B,2]
                          const int*    __restrict__ sc,    // [R,16]
                          float*        __restrict__ ps_out,
                          float*        __restrict__ nc_out)
{
    __shared__ float4 bv_sh[256];   // best_val for this block's 1024 r's

    const int tid  = threadIdx.x;
    const int b    = blockIdx.x >> 2;            // 4 blocks per batch row
    const int rqb  = (blockIdx.x & 3) << 8;      // base rq of this block
    const int rq   = rqb + tid;                  // this thread's rq (0..1023)

    const float4* __restrict__ cbv = (const float4*)(cost + (size_t)b * S_);

    // ---- Phase 1: min/argmin over d (strict '<' => first occurrence, jnp.argmin)
    float4 best = cbv[rq];
    int bdx = 0, bdy = 0, bdz = 0, bdw = 0;
    #pragma unroll
    for (int d = 1; d < D_; ++d) {
        float4 v = cbv[d * (R_ / 4) + rq];
        if (v.x < best.x) { best.x = v.x; bdx = d; }
        if (v.y < best.y) { best.y = v.y; bdy = d; }
        if (v.z < best.z) { best.z = v.z; bdz = d; }
        if (v.w < best.w) { best.w = v.w; bdw = d; }
    }

    bv_sh[tid] = best;

    // prev_state[b, r] = sc[r, best_idx] (sc is L2-resident); coalesced float4 store
    if (ps_out) {
        const int r0 = rq << 2;
        float4 ps;
        ps.x = (float)__ldg(&sc[(r0 + 0) * D_ + bdx]);
        ps.y = (float)__ldg(&sc[(r0 + 1) * D_ + bdy]);
        ps.z = (float)__ldg(&sc[(r0 + 2) * D_ + bdz]);
        ps.w = (float)__ldg(&sc[(r0 + 3) * D_ + bdw]);
        ((float4*)ps_out)[(size_t)b * (R_ / 4) + rq] = ps;
    }

    __syncthreads();

    // ---- Phase 2: coalesced new_cost epilogue
    if (nc_out) {
        const float o0 = __ldg(&orig[2 * b + 0]);
        const float o1 = __ldg(&orig[2 * b + 1]);

        // block's s range: [rqb*16*4, +16384); as float4: base index rqb*16
        const size_t s4_base = (size_t)rqb * 16;                 // float4 index into row
        float4* __restrict__ nc = (float4*)(nc_out + (size_t)b * S_) + s4_base;
        const float4* __restrict__ lv = (const float4*)lut + s4_base * 2; // 2 lut-f4 per nc-f4
        const float* __restrict__ bvf = (const float*)bv_sh;     // bv[r_local], r_local in [0,1024)

        #pragma unroll
        for (int it = 0; it < 16; ++it) {
            const int idx = it * 256 + tid;      // float4 index within block's span
            // s0 = 4*idx; r_local = s0>>4 = idx>>2 ; d = s0&15 spans one r per float4
            const float bv = bvf[idx >> 2];
            float4 l0 = __ldg(&lv[2 * idx + 0]); // lut pairs for s0, s0+1
            float4 l1 = __ldg(&lv[2 * idx + 1]); // lut pairs for s0+2, s0+3
            float4 o;
            float dx, dy;
            dx = l0.x - o0; dy = l0.y - o1; o.x = fmaf(dx, dx, dy * dy) + bv;
            dx = l0.z - o0; dy = l0.w - o1; o.y = fmaf(dx, dx, dy * dy) + bv;
            dx = l1.x - o0; dy = l1.y - o1; o.z = fmaf(dx, dx, dy * dy) + bv;
            dx = l1.z - o0; dy = l1.w - o1; o.w = fmaf(dx, dx, dy * dy) + bv;
            nc[idx] = o;
        }
    }
}

extern "C" void kernel_launch(void* const* d_in, const int* in_sizes, int n_in,
                              void* d_out, int out_size)
{
    const float* lut  = (const float*)d_in[0];
    const float* cost = (const float*)d_in[1];
    const float* orig = (const float*)d_in[2];
    const int*   sc   = (const int*)d_in[3];
    float* out = (float*)d_out;

    float* ps_out = nullptr;
    float* nc_out = nullptr;
    const size_t osz = (size_t)out_size;
    if (osz >= (size_t)PS_ + NC_) {
        ps_out = out;
        nc_out = out + PS_;
    } else if (osz == NC_) {
        nc_out = out;
    } else {
        ps_out = out;
    }

    trellis_fused_kernel<<<B_ * 4, 256>>>(lut, cost, orig, sc, ps_out, nc_out);
}

// round 5
// speedup vs baseline: 2.3211x; 1.5081x over previous
#include <cuda_runtime.h>
#include <cuda_bf16.h>
#include <cstddef>

// Problem constants (fixed by reference: L=16, KV=4, V=2, B=512)
#define S_  65536
#define R_  4096
#define D_  16
#define B_  512
#define PS_ (B_ * R_)          // 2097152
#define NC_ ((size_t)B_ * S_)  // 33554432

// Block = 256 threads = 1/4 of one batch row (1024 r's, 16384 s's).
// Phase 1: per-thread min/argmin over d for 4 consecutive r's (coalesced
//          strided float4 loads, MLP=16). prev_state is computed ARITHMETICALLY:
//          state_candidates[r,d] = r + (d<<12) by construction, so no gather.
// Phase 2: warp covers 128 s per iter. Two fully-coalesced float4 lut loads
//          (4 wf each); the thread that loads lut f4 j (= states 2j,2j+1)
//          writes those two nc values as one coalesced float2 store (2 wf).
//          12 wf/iter = sector minimum. best_val broadcast from smem.
__global__ __launch_bounds__(256)
void trellis_fused_kernel(const float*  __restrict__ lut,   // [S,2]
                          const float*  __restrict__ cost,  // [B,S]
                          const float*  __restrict__ orig,  // [B,2]
                          float*        __restrict__ ps_out,
                          float*        __restrict__ nc_out)
{
    __shared__ float bvf[1024];     // best_val for this block's 1024 local r's

    const int tid  = threadIdx.x;
    const int lane = tid & 31;
    const int w    = tid >> 5;                   // warp id 0..7
    const int b    = blockIdx.x >> 2;            // 4 blocks per batch row
    const int q    = blockIdx.x & 3;             // quarter of the row
    const int rq   = (q << 8) + tid;             // global rq in [0,1024)

    const float4* __restrict__ cbv = (const float4*)(cost + (size_t)b * S_);

    // ---- Phase 1: min/argmin over d (strict '<' => first occurrence, jnp.argmin)
    float4 best = cbv[rq];
    int bdx = 0, bdy = 0, bdz = 0, bdw = 0;
    #pragma unroll
    for (int d = 1; d < D_; ++d) {
        float4 v = cbv[d * (R_ / 4) + rq];
        if (v.x < best.x) { best.x = v.x; bdx = d; }
        if (v.y < best.y) { best.y = v.y; bdy = d; }
        if (v.z < best.z) { best.z = v.z; bdz = d; }
        if (v.w < best.w) { best.w = v.w; bdw = d; }
    }

    // smem layout: bvf[r_local] with r_local = tid*4 + j
    ((float4*)bvf)[tid] = best;

    // prev_state[b,r] = sc[r,best_idx] = r + (best_idx << 12)  (pure ALU)
    if (ps_out) {
        const int r0 = rq << 2;   // global r base for this thread
        float4 ps;
        ps.x = (float)(r0 + 0 + (bdx << 12));
        ps.y = (float)(r0 + 1 + (bdy << 12));
        ps.z = (float)(r0 + 2 + (bdz << 12));
        ps.w = (float)(r0 + 3 + (bdw << 12));
        ((float4*)ps_out)[(size_t)b * (R_ / 4) + rq] = ps;
    }

    __syncthreads();

    // ---- Phase 2: coalesced new_cost epilogue
    if (nc_out) {
        const float o0 = __ldg(&orig[2 * b + 0]);
        const float o1 = __ldg(&orig[2 * b + 1]);

        const float4* __restrict__ lvf4 = (const float4*)lut;     // f4 j = states 2j,2j+1
        float2* __restrict__ nc2 = (float2*)(nc_out + (size_t)b * S_);

        // warp's half-state (float2/lut-f4) index base: s_base/2
        const int hb = q * 8192 + w * 1024;

        #pragma unroll
        for (int it = 0; it < 16; ++it) {
            const int jb = hb + it * 64;         // window of 64 lut f4s (128 s)
            float4 A  = __ldg(&lvf4[jb + lane]);        // states 2(jb+lane), +1
            float4 Bv = __ldg(&lvf4[jb + 32 + lane]);   // states 2(jb+32+lane), +1

            // r_local for A's states: (s - q*16384)>>4
            const int rbase = w * 128 + it * 8 + (lane >> 3);
            const float bvA = bvf[rbase];
            const float bvB = bvf[rbase + 4];

            float dx, dy;
            float2 oA, oB;
            dx = A.x  - o0; dy = A.y  - o1; oA.x = fmaf(dx, dx, dy * dy) + bvA;
            dx = A.z  - o0; dy = A.w  - o1; oA.y = fmaf(dx, dx, dy * dy) + bvA;
            dx = Bv.x - o0; dy = Bv.y - o1; oB.x = fmaf(dx, dx, dy * dy) + bvB;
            dx = Bv.z - o0; dy = Bv.w - o1; oB.y = fmaf(dx, dx, dy * dy) + bvB;

            nc2[jb + lane]      = oA;            // coalesced float2 stores
            nc2[jb + 32 + lane] = oB;
        }
    }
}

extern "C" void kernel_launch(void* const* d_in, const int* in_sizes, int n_in,
                              void* d_out, int out_size)
{
    const float* lut  = (const float*)d_in[0];
    const float* cost = (const float*)d_in[1];
    const float* orig = (const float*)d_in[2];
    float* out = (float*)d_out;

    float* ps_out = nullptr;
    float* nc_out = nullptr;
    const size_t osz = (size_t)out_size;
    if (osz >= (size_t)PS_ + NC_) {
        ps_out = out;
        nc_out = out + PS_;
    } else if (osz == NC_) {
        nc_out = out;
    } else {
        ps_out = out;
    }

    trellis_fused_kernel<<<B_ * 4, 256>>>(lut, cost, orig, ps_out, nc_out);
}